// round 9
// baseline (speedup 1.0000x reference)
#include <cuda_runtime.h>
#include <cstdint>

#define B_  8
#define C_  128
#define H_  192
#define W_  448
#define ND  49

#define TX  32
#define TY  16
#define KC  8
#define NCHUNK (C_ / KC)
#define NT  448          // 14 warps: (dj 0..6) x (x-half 0..1)

#define S1_ROW 36
#define S1_CH  (TY * S1_ROW)        // 576
#define S2_ROW 44                   // padded col = logical x + 4
#define S2_CH  ((TY + 6) * S2_ROW)  // 968
#define S1_SIZE (KC * S1_CH)        // 4608
#define S2_SIZE (KC * S2_CH)        // 7744
#define BUF_SIZE (S1_SIZE + S2_SIZE)               // 12352 floats
#define SMEM_BYTES (2 * BUF_SIZE * sizeof(float))  // 98816 B

typedef unsigned long long ull;

__device__ __forceinline__ uint32_t sptr(const void* p) {
    return (uint32_t)__cvta_generic_to_shared(p);
}
__device__ __forceinline__ void cp16(void* dst, const float* src, bool pred) {
    int bytes = pred ? 16 : 0;
    asm volatile("cp.async.cg.shared.global [%0], [%1], 16, %2;\n"
                 :: "r"(sptr(dst)), "l"(src), "r"(bytes));
}
__device__ __forceinline__ void cp4(void* dst, const float* src, bool pred) {
    int bytes = pred ? 4 : 0;
    asm volatile("cp.async.ca.shared.global [%0], [%1], 4, %2;\n"
                 :: "r"(sptr(dst)), "l"(src), "r"(bytes));
}
__device__ __forceinline__ void cp_commit() {
    asm volatile("cp.async.commit_group;\n" ::: "memory");
}
__device__ __forceinline__ void lds2(ull& a, ull& b, uint32_t addr) {
    asm volatile("ld.shared.v2.u64 {%0,%1}, [%2];"
                 : "=l"(a), "=l"(b) : "r"(addr));
}
__device__ __forceinline__ void fma2(ull& d, ull a, ull b) {
    asm("fma.rn.f32x2 %0, %1, %2, %0;" : "+l"(d) : "l"(a), "l"(b));
}
__device__ __forceinline__ void unpack2(float& lo, float& hi, ull v) {
    asm("mov.b64 {%0,%1}, %2;" : "=f"(lo), "=f"(hi) : "l"(v));
}

// All index math is shifts/masks (no integer division in the hot path).
__device__ __forceinline__ void load_chunk(
    float* __restrict__ s1, float* __restrict__ s2,
    const float* __restrict__ fbase, const float* __restrict__ sbase,
    int c0, int x0, int y0, int tid)
{
    const size_t HW = (size_t)H_ * W_;
    // ---- first tile: 8ch x 16 rows x 8 q = 1024 units ----
#pragma unroll
    for (int it = 0; it < 3; ++it) {
        int u = tid + it * NT;
        if (it < 2 || u < 1024) {
            int c = u >> 7;
            int row = (u >> 3) & 15;
            int q = u & 7;
            const float* src = fbase + (size_t)(c0 + c) * HW + (size_t)(y0 + row) * W_ + x0 + q * 4;
            cp16(s1 + c * S1_CH + row * S1_ROW + q * 4, src, true);
        }
    }
    // ---- second interior: 8ch x rows(22, padded 32) x 8 q = 2048 padded units ----
#pragma unroll
    for (int it = 0; it < 5; ++it) {
        int u = tid + it * NT;
        if (it < 4 || u < 2048) {
            int c = u >> 8;
            int row = (u >> 3) & 31;
            int q = u & 7;
            if (row < 22) {
                int gy = y0 - 3 + row;
                bool p = (gy >= 0) && (gy < H_);
                int gyc = gy < 0 ? 0 : (gy >= H_ ? H_ - 1 : gy);
                const float* src = sbase + (size_t)(c0 + c) * HW + (size_t)gyc * W_ + x0 + q * 4;
                cp16(s2 + c * S2_CH + row * S2_ROW + 4 + q * 4, src, p);
            }
        }
    }
    // ---- second edges: 8ch x rows(22, padded 32) x e(6, padded 8) ----
#pragma unroll
    for (int it = 0; it < 5; ++it) {
        int u = tid + it * NT;
        if (it < 4 || u < 2048) {
            int c = u >> 8;
            int row = (u >> 3) & 31;
            int e = u & 7;
            if (row < 22 && e < 6) {
                int x = (e < 3) ? (e - 3) : (TX + e - 3);
                int gy = y0 - 3 + row;
                int gx = x0 + x;
                bool p = (gy >= 0) && (gy < H_) && (gx >= 0) && (gx < W_);
                int gyc = gy < 0 ? 0 : (gy >= H_ ? H_ - 1 : gy);
                int gxc = gx < 0 ? 0 : (gx >= W_ ? W_ - 1 : gx);
                const float* src = sbase + (size_t)(c0 + c) * HW + (size_t)gyc * W_ + gxc;
                cp4(s2 + c * S2_CH + row * S2_ROW + (x + 4), src, p);
            }
        }
    }
}

__global__ void __launch_bounds__(NT, 1)
corr_kernel(const float* __restrict__ first,
            const float* __restrict__ second,
            float* __restrict__ out)
{
    extern __shared__ float smem[];
    const int tid = threadIdx.x;
    const int wid = tid >> 5;                 // 0..13
    const int lane = tid & 31;
    const int dj = (wid < 7) ? wid : wid - 7; // row displacement 0..6
    const int xh = (wid < 7) ? 0 : 1;         // x-half
    const int txl = lane & 1;                 // 0..1
    const int tyl = lane >> 1;                // 0..15
    const int xl = xh * 16 + txl * 8;         // local x base, owns 8 px
    const int bx = blockIdx.x, by = blockIdx.y, b = blockIdx.z;
    const int x0 = bx * TX, y0 = by * TY;

    const size_t HW = (size_t)H_ * W_;
    const float* fbase = first  + (size_t)b * C_ * HW;
    const float* sbase = second + (size_t)b * C_ * HW;

    const uint32_t smem_base = sptr(smem);
    const uint32_t s1_thr = smem_base + (uint32_t)(tyl * S1_ROW + xl) * 4;
    const uint32_t s2_thr = smem_base + (uint32_t)S1_SIZE * 4
                          + (uint32_t)((tyl + dj) * S2_ROW + xl) * 4;

    ull acc2[28];   // [di 0..6][pair 0..3]
#pragma unroll
    for (int i = 0; i < 28; ++i) acc2[i] = 0ull;

    load_chunk(smem, smem + S1_SIZE, fbase, sbase, 0, x0, y0, tid);
    cp_commit();

#pragma unroll 1
    for (int k = 0; k < NCHUNK; ++k) {
        if (k < NCHUNK - 1) {
            float* nb = smem + ((k + 1) & 1) * BUF_SIZE;
            load_chunk(nb, nb + S1_SIZE, fbase, sbase, (k + 1) * KC, x0, y0, tid);
            cp_commit();
            asm volatile("cp.async.wait_group 1;\n" ::: "memory");
        } else {
            asm volatile("cp.async.wait_group 0;\n" ::: "memory");
        }
        __syncthreads();

        const uint32_t boff = (uint32_t)((k & 1) * BUF_SIZE * 4);
        uint32_t a1 = s1_thr + boff;
        uint32_t a2 = s2_thr + boff;

#pragma unroll 2
        for (int c = 0; c < KC; ++c) {
            ull f[4];
            lds2(f[0], f[1], a1);
            lds2(f[2], f[3], a1 + 16);
            ull e[8];
            lds2(e[0], e[1], a2);
            lds2(e[2], e[3], a2 + 16);
            lds2(e[4], e[5], a2 + 32);
            lds2(e[6], e[7], a2 + 48);
            a1 += S1_CH * 4;
            a2 += S2_CH * 4;

            ull o[7];
#pragma unroll
            for (int t = 0; t < 7; ++t)
                o[t] = (e[t] >> 32) | (e[t + 1] << 32);

#pragma unroll
            for (int d = 0; d < 7; ++d) {
#pragma unroll
                for (int pp = 0; pp < 4; ++pp) {
                    ull vp = (d & 1) ? e[(d + 1) / 2 + pp] : o[d / 2 + pp];
                    fma2(acc2[d * 4 + pp], f[pp], vp);
                }
            }
        }
        __syncthreads();
    }

    // epilogue: mean over channels; this warp owns flattened d = dj*7 + di
    const float invC = 1.0f / (float)C_;
    const int y = y0 + tyl;
    const int x = x0 + xl;
#pragma unroll
    for (int d = 0; d < 7; ++d) {
        float r[8];
#pragma unroll
        for (int pp = 0; pp < 4; ++pp)
            unpack2(r[pp * 2], r[pp * 2 + 1], acc2[d * 4 + pp]);
        float* op = out + (((size_t)b * ND + dj * 7 + d) * H_ + y) * W_ + x;
        float4 o0, o1;
        o0.x = r[0] * invC; o0.y = r[1] * invC;
        o0.z = r[2] * invC; o0.w = r[3] * invC;
        o1.x = r[4] * invC; o1.y = r[5] * invC;
        o1.z = r[6] * invC; o1.w = r[7] * invC;
        ((float4*)op)[0] = o0;
        ((float4*)op)[1] = o1;
    }
}

extern "C" void kernel_launch(void* const* d_in, const int* in_sizes, int n_in,
                              void* d_out, int out_size)
{
    const float* first  = (const float*)d_in[0];
    const float* second = (const float*)d_in[1];
    float* out = (float*)d_out;

    cudaFuncSetAttribute(corr_kernel,
                         cudaFuncAttributeMaxDynamicSharedMemorySize,
                         (int)SMEM_BYTES);

    dim3 grid(W_ / TX, H_ / TY, B_);   // 14 x 12 x 8 = 1344 CTAs
    dim3 block(NT);
    corr_kernel<<<grid, block, SMEM_BYTES>>>(first, second, out);
}

// round 10
// speedup vs baseline: 1.3291x; 1.3291x over previous
#include <cuda_runtime.h>
#include <cstdint>

#define B_  8
#define C_  128
#define H_  192
#define W_  448
#define ND  49

#define TX  32
#define TY  16
#define KC  8
#define NCHUNK (C_ / KC)
#define NT  448          // 14 warps: (dj 0..6) x (x-half 0..1)

#define S1_ROW 36                   // 36*4B=144B: slot stride 9 (odd) -> conflict-free
#define S1_CH  (TY * S1_ROW)        // 576
#define S2_ROW 44                   // 44*4B=176B: slot stride 11 (odd) -> conflict-free
#define S2_CH  ((TY + 6) * S2_ROW)  // 968
#define S1_SIZE (KC * S1_CH)        // 4608
#define S2_SIZE (KC * S2_CH)        // 7744
#define BUF_SIZE (S1_SIZE + S2_SIZE)               // 12352 floats
#define SMEM_BYTES (2 * BUF_SIZE * sizeof(float))  // 98816 B

typedef unsigned long long ull;

__device__ __forceinline__ uint32_t sptr(const void* p) {
    return (uint32_t)__cvta_generic_to_shared(p);
}
__device__ __forceinline__ void cp16(void* dst, const float* src, bool pred) {
    int bytes = pred ? 16 : 0;
    asm volatile("cp.async.cg.shared.global [%0], [%1], 16, %2;\n"
                 :: "r"(sptr(dst)), "l"(src), "r"(bytes));
}
__device__ __forceinline__ void cp4(void* dst, const float* src, bool pred) {
    int bytes = pred ? 4 : 0;
    asm volatile("cp.async.ca.shared.global [%0], [%1], 4, %2;\n"
                 :: "r"(sptr(dst)), "l"(src), "r"(bytes));
}
__device__ __forceinline__ void cp_commit() {
    asm volatile("cp.async.commit_group;\n" ::: "memory");
}
__device__ __forceinline__ void lds2(ull& a, ull& b, uint32_t addr) {
    asm volatile("ld.shared.v2.u64 {%0,%1}, [%2];"
                 : "=l"(a), "=l"(b) : "r"(addr));
}
__device__ __forceinline__ void fma2(ull& d, ull a, ull b) {
    asm("fma.rn.f32x2 %0, %1, %2, %0;" : "+l"(d) : "l"(a), "l"(b));
}
__device__ __forceinline__ void unpack2(float& lo, float& hi, ull v) {
    asm("mov.b64 {%0,%1}, %2;" : "=f"(lo), "=f"(hi) : "l"(v));
}

// All index math is shifts/masks (no integer division in the hot path).
__device__ __forceinline__ void load_chunk(
    float* __restrict__ s1, float* __restrict__ s2,
    const float* __restrict__ fbase, const float* __restrict__ sbase,
    int c0, int x0, int y0, int tid)
{
    const size_t HW = (size_t)H_ * W_;
    // ---- first tile: 8ch x 16 rows x 8 q = 1024 units ----
#pragma unroll
    for (int it = 0; it < 3; ++it) {
        int u = tid + it * NT;
        if (it < 2 || u < 1024) {
            int c = u >> 7;
            int row = (u >> 3) & 15;
            int q = u & 7;
            const float* src = fbase + (size_t)(c0 + c) * HW + (size_t)(y0 + row) * W_ + x0 + q * 4;
            cp16(s1 + c * S1_CH + row * S1_ROW + q * 4, src, true);
        }
    }
    // ---- second interior: 8ch x rows(22, padded 32) x 8 q ----
#pragma unroll
    for (int it = 0; it < 5; ++it) {
        int u = tid + it * NT;
        if (it < 4 || u < 2048) {
            int c = u >> 8;
            int row = (u >> 3) & 31;
            int q = u & 7;
            if (row < 22) {
                int gy = y0 - 3 + row;
                bool p = (gy >= 0) && (gy < H_);
                int gyc = gy < 0 ? 0 : (gy >= H_ ? H_ - 1 : gy);
                const float* src = sbase + (size_t)(c0 + c) * HW + (size_t)gyc * W_ + x0 + q * 4;
                cp16(s2 + c * S2_CH + row * S2_ROW + 4 + q * 4, src, p);
            }
        }
    }
    // ---- second edges: 8ch x rows(22, padded 32) x e(6, padded 8) ----
#pragma unroll
    for (int it = 0; it < 5; ++it) {
        int u = tid + it * NT;
        if (it < 4 || u < 2048) {
            int c = u >> 8;
            int row = (u >> 3) & 31;
            int e = u & 7;
            if (row < 22 && e < 6) {
                int x = (e < 3) ? (e - 3) : (TX + e - 3);
                int gy = y0 - 3 + row;
                int gx = x0 + x;
                bool p = (gy >= 0) && (gy < H_) && (gx >= 0) && (gx < W_);
                int gyc = gy < 0 ? 0 : (gy >= H_ ? H_ - 1 : gy);
                int gxc = gx < 0 ? 0 : (gx >= W_ ? W_ - 1 : gx);
                const float* src = sbase + (size_t)(c0 + c) * HW + (size_t)gyc * W_ + gxc;
                cp4(s2 + c * S2_CH + row * S2_ROW + (x + 4), src, p);
            }
        }
    }
}

__global__ void __launch_bounds__(NT, 1)
corr_kernel(const float* __restrict__ first,
            const float* __restrict__ second,
            float* __restrict__ out)
{
    extern __shared__ float smem[];
    const int tid = threadIdx.x;
    const int wid = tid >> 5;                 // 0..13
    const int lane = tid & 31;
    const int dj = (wid < 7) ? wid : wid - 7; // row displacement 0..6
    const int xh = (wid < 7) ? 0 : 1;         // x-half
    // Conflict-free lane map: 8-lane LDS wavefront = 8 CONSECUTIVE rows.
    const int tyl = lane & 15;                // 0..15, one y-row
    const int txl = lane >> 4;                // 0..1
    const int xl = xh * 16 + txl * 8;         // local x base, owns 8 px
    const int bx = blockIdx.x, by = blockIdx.y, b = blockIdx.z;
    const int x0 = bx * TX, y0 = by * TY;

    const size_t HW = (size_t)H_ * W_;
    const float* fbase = first  + (size_t)b * C_ * HW;
    const float* sbase = second + (size_t)b * C_ * HW;

    const uint32_t smem_base = sptr(smem);
    const uint32_t s1_thr = smem_base + (uint32_t)(tyl * S1_ROW + xl) * 4;
    const uint32_t s2_thr = smem_base + (uint32_t)S1_SIZE * 4
                          + (uint32_t)((tyl + dj) * S2_ROW + xl) * 4;

    ull acc2[28];   // [di 0..6][pair 0..3]
#pragma unroll
    for (int i = 0; i < 28; ++i) acc2[i] = 0ull;

    load_chunk(smem, smem + S1_SIZE, fbase, sbase, 0, x0, y0, tid);
    cp_commit();

#pragma unroll 1
    for (int k = 0; k < NCHUNK; ++k) {
        if (k < NCHUNK - 1) {
            float* nb = smem + ((k + 1) & 1) * BUF_SIZE;
            load_chunk(nb, nb + S1_SIZE, fbase, sbase, (k + 1) * KC, x0, y0, tid);
            cp_commit();
            asm volatile("cp.async.wait_group 1;\n" ::: "memory");
        } else {
            asm volatile("cp.async.wait_group 0;\n" ::: "memory");
        }
        __syncthreads();

        const uint32_t boff = (uint32_t)((k & 1) * BUF_SIZE * 4);
        uint32_t a1 = s1_thr + boff;
        uint32_t a2 = s2_thr + boff;

#pragma unroll 2
        for (int c = 0; c < KC; ++c) {
            ull f[4];
            lds2(f[0], f[1], a1);
            lds2(f[2], f[3], a1 + 16);
            ull e[8];
            lds2(e[0], e[1], a2);
            lds2(e[2], e[3], a2 + 16);
            lds2(e[4], e[5], a2 + 32);
            lds2(e[6], e[7], a2 + 48);
            a1 += S1_CH * 4;
            a2 += S2_CH * 4;

            ull o[7];
#pragma unroll
            for (int t = 0; t < 7; ++t)
                o[t] = (e[t] >> 32) | (e[t + 1] << 32);

#pragma unroll
            for (int d = 0; d < 7; ++d) {
#pragma unroll
                for (int pp = 0; pp < 4; ++pp) {
                    ull vp = (d & 1) ? e[(d + 1) / 2 + pp] : o[d / 2 + pp];
                    fma2(acc2[d * 4 + pp], f[pp], vp);
                }
            }
        }
        __syncthreads();
    }

    // epilogue: mean over channels; this warp owns flattened d = dj*7 + di
    const float invC = 1.0f / (float)C_;
    const int y = y0 + tyl;
    const int x = x0 + xl;
#pragma unroll
    for (int d = 0; d < 7; ++d) {
        float r[8];
#pragma unroll
        for (int pp = 0; pp < 4; ++pp)
            unpack2(r[pp * 2], r[pp * 2 + 1], acc2[d * 4 + pp]);
        float* op = out + (((size_t)b * ND + dj * 7 + d) * H_ + y) * W_ + x;
        float4 o0, o1;
        o0.x = r[0] * invC; o0.y = r[1] * invC;
        o0.z = r[2] * invC; o0.w = r[3] * invC;
        o1.x = r[4] * invC; o1.y = r[5] * invC;
        o1.z = r[6] * invC; o1.w = r[7] * invC;
        ((float4*)op)[0] = o0;
        ((float4*)op)[1] = o1;
    }
}

extern "C" void kernel_launch(void* const* d_in, const int* in_sizes, int n_in,
                              void* d_out, int out_size)
{
    const float* first  = (const float*)d_in[0];
    const float* second = (const float*)d_in[1];
    float* out = (float*)d_out;

    cudaFuncSetAttribute(corr_kernel,
                         cudaFuncAttributeMaxDynamicSharedMemorySize,
                         (int)SMEM_BYTES);

    dim3 grid(W_ / TX, H_ / TY, B_);   // 14 x 12 x 8 = 1344 CTAs
    dim3 block(NT);
    corr_kernel<<<grid, block, SMEM_BYTES>>>(first, second, out);
}

// round 11
// speedup vs baseline: 1.5744x; 1.1846x over previous
#include <cuda_runtime.h>
#include <cstdint>

#define B_  8
#define C_  128
#define H_  192
#define W_  448
#define ND  49

#define TX  32
#define TY  8
#define KC  8
#define NCHUNK (C_ / KC)
#define NT  224          // 7 warps, warp = dj

#define S1_ROW 36                   // 144B rows: slot stride 9 (odd) -> conflict-free
#define S1_CH  (TY * S1_ROW)        // 288
#define S2_ROW 44                   // 176B rows: slot stride 11 (odd) -> conflict-free
#define S2_CH  ((TY + 6) * S2_ROW)  // 14*44 = 616
#define S1_SIZE (KC * S1_CH)        // 2304
#define S2_SIZE (KC * S2_CH)        // 4928
#define BUF_SIZE (S1_SIZE + S2_SIZE)               // 7232 floats
#define SMEM_BYTES (2 * BUF_SIZE * sizeof(float))  // 57856 B per CTA

typedef unsigned long long ull;

__device__ __forceinline__ uint32_t sptr(const void* p) {
    return (uint32_t)__cvta_generic_to_shared(p);
}
__device__ __forceinline__ void cp16(void* dst, const float* src, bool pred) {
    int bytes = pred ? 16 : 0;
    asm volatile("cp.async.cg.shared.global [%0], [%1], 16, %2;\n"
                 :: "r"(sptr(dst)), "l"(src), "r"(bytes));
}
__device__ __forceinline__ void cp_commit() {
    asm volatile("cp.async.commit_group;\n" ::: "memory");
}
__device__ __forceinline__ void lds2(ull& a, ull& b, uint32_t addr) {
    asm volatile("ld.shared.v2.u64 {%0,%1}, [%2];"
                 : "=l"(a), "=l"(b) : "r"(addr));
}
__device__ __forceinline__ void fma2(ull& d, ull a, ull b) {
    asm("fma.rn.f32x2 %0, %1, %2, %0;" : "+l"(d) : "l"(a), "l"(b));
}
__device__ __forceinline__ void unpack2(float& lo, float& hi, ull v) {
    asm("mov.b64 {%0,%1}, %2;" : "=f"(lo), "=f"(hi) : "l"(v));
}

// Pure shift/mask indexing; 'second' rows loaded as 11 full float4 chunks
// covering padded cols [0,44) = logical x [-4,40); OOB chunks zfill (== jnp.pad).
__device__ __forceinline__ void load_chunk(
    float* __restrict__ s1, float* __restrict__ s2,
    const float* __restrict__ fbase, const float* __restrict__ sbase,
    int c0, int x0, int y0, int tid)
{
    const size_t HW = (size_t)H_ * W_;
    // ---- first tile: 8ch x 8 rows x 8 q = 512 units ----
#pragma unroll
    for (int it = 0; it < 3; ++it) {
        int u = tid + it * NT;
        if (it < 2 || u < 512) {
            int c = u >> 6;
            int row = (u >> 3) & 7;
            int q = u & 7;
            const float* src = fbase + (size_t)(c0 + c) * HW + (size_t)(y0 + row) * W_ + x0 + q * 4;
            cp16(s1 + c * S1_CH + row * S1_ROW + q * 4, src, true);
        }
    }
    // ---- second tile: per channel exactly 14 rows x 16 slots = 224 = NT ----
    const int row = tid >> 4;      // 0..13
    const int q   = tid & 15;      // 0..15, use q < 11
    if (q < 11) {
        const int gy = y0 - 3 + row;
        const int gx = x0 - 4 + q * 4;
        const bool p = (gy >= 0) && (gy < H_) && (gx >= 0) && (gx < W_);
        const int gyc = gy < 0 ? 0 : (gy >= H_ ? H_ - 1 : gy);
        const int gxc = gx < 0 ? 0 : (gx >= W_ ? W_ - 1 : gx);
        const float* src0 = sbase + (size_t)c0 * HW + (size_t)gyc * W_ + gxc;
        float* dst0 = s2 + row * S2_ROW + q * 4;
#pragma unroll
        for (int c = 0; c < KC; ++c)
            cp16(dst0 + c * S2_CH, src0 + c * HW, p);
    }
}

__global__ void __launch_bounds__(NT, 2)
corr_kernel(const float* __restrict__ first,
            const float* __restrict__ second,
            float* __restrict__ out)
{
    extern __shared__ float smem[];
    const int tid = threadIdx.x;
    const int dj = tid >> 5;                  // warp = row displacement 0..6
    const int lane = tid & 31;
    // Conflict-free lane map: 8-lane LDS wavefront = 8 consecutive rows.
    const int tyl = lane & 7;                 // 0..7, one y-row
    const int txl = lane >> 3;                // 0..3, owns 8 x-pixels
    const int xl = txl * 8;
    const int bx = blockIdx.x, by = blockIdx.y, b = blockIdx.z;
    const int x0 = bx * TX, y0 = by * TY;

    const size_t HW = (size_t)H_ * W_;
    const float* fbase = first  + (size_t)b * C_ * HW;
    const float* sbase = second + (size_t)b * C_ * HW;

    const uint32_t smem_base = sptr(smem);
    const uint32_t s1_thr = smem_base + (uint32_t)(tyl * S1_ROW + xl) * 4;
    const uint32_t s2_thr = smem_base + (uint32_t)S1_SIZE * 4
                          + (uint32_t)((tyl + dj) * S2_ROW + xl) * 4;

    ull acc2[28];   // [di 0..6][px-pair 0..3]
#pragma unroll
    for (int i = 0; i < 28; ++i) acc2[i] = 0ull;

    load_chunk(smem, smem + S1_SIZE, fbase, sbase, 0, x0, y0, tid);
    cp_commit();

#pragma unroll 1
    for (int k = 0; k < NCHUNK; ++k) {
        if (k < NCHUNK - 1) {
            float* nb = smem + ((k + 1) & 1) * BUF_SIZE;
            load_chunk(nb, nb + S1_SIZE, fbase, sbase, (k + 1) * KC, x0, y0, tid);
            cp_commit();
            asm volatile("cp.async.wait_group 1;\n" ::: "memory");
        } else {
            asm volatile("cp.async.wait_group 0;\n" ::: "memory");
        }
        __syncthreads();

        const uint32_t boff = (uint32_t)((k & 1) * BUF_SIZE * 4);
        uint32_t a1 = s1_thr + boff;
        uint32_t a2 = s2_thr + boff;

#pragma unroll 2
        for (int c = 0; c < KC; ++c) {
            ull f[4];
            lds2(f[0], f[1], a1);
            lds2(f[2], f[3], a1 + 16);
            ull e[8];
            lds2(e[0], e[1], a2);
            lds2(e[2], e[3], a2 + 16);
            lds2(e[4], e[5], a2 + 32);
            lds2(e[6], e[7], a2 + 48);
            a1 += S1_CH * 4;
            a2 += S2_CH * 4;

            ull o[7];
#pragma unroll
            for (int t = 0; t < 7; ++t)
                o[t] = (e[t] >> 32) | (e[t + 1] << 32);

#pragma unroll
            for (int d = 0; d < 7; ++d) {
#pragma unroll
                for (int pp = 0; pp < 4; ++pp) {
                    ull vp = (d & 1) ? e[(d + 1) / 2 + pp] : o[d / 2 + pp];
                    fma2(acc2[d * 4 + pp], f[pp], vp);
                }
            }
        }
        __syncthreads();
    }

    // epilogue: mean over channels; warp dj owns flattened d = dj*7 + di
    const float invC = 1.0f / (float)C_;
    const int y = y0 + tyl;
    const int x = x0 + xl;
#pragma unroll
    for (int d = 0; d < 7; ++d) {
        float r[8];
#pragma unroll
        for (int pp = 0; pp < 4; ++pp)
            unpack2(r[pp * 2], r[pp * 2 + 1], acc2[d * 4 + pp]);
        float* op = out + (((size_t)b * ND + dj * 7 + d) * H_ + y) * W_ + x;
        float4 o0, o1;
        o0.x = r[0] * invC; o0.y = r[1] * invC;
        o0.z = r[2] * invC; o0.w = r[3] * invC;
        o1.x = r[4] * invC; o1.y = r[5] * invC;
        o1.z = r[6] * invC; o1.w = r[7] * invC;
        ((float4*)op)[0] = o0;
        ((float4*)op)[1] = o1;
    }
}

extern "C" void kernel_launch(void* const* d_in, const int* in_sizes, int n_in,
                              void* d_out, int out_size)
{
    const float* first  = (const float*)d_in[0];
    const float* second = (const float*)d_in[1];
    float* out = (float*)d_out;

    cudaFuncSetAttribute(corr_kernel,
                         cudaFuncAttributeMaxDynamicSharedMemorySize,
                         (int)SMEM_BYTES);

    dim3 grid(W_ / TX, H_ / TY, B_);   // 14 x 24 x 8 = 2688 CTAs
    dim3 block(NT);
    corr_kernel<<<grid, block, SMEM_BYTES>>>(first, second, out);
}

// round 12
// speedup vs baseline: 1.6419x; 1.0429x over previous
#include <cuda_runtime.h>
#include <cstdint>

#define B_  8
#define C_  128
#define H_  192
#define W_  448
#define ND  49

#define TX  32
#define TY  8
#define KC  8
#define NCHUNK (C_ / KC)
#define NT  224          // 7 warps, warp = dj

#define S1_ROW 36                   // 144B rows: slot stride 9 (odd) -> conflict-free
#define S1_CH  (TY * S1_ROW)        // 288
#define S2_ROW 44                   // 176B rows: slot stride 11 (odd) -> conflict-free
#define S2_CH  ((TY + 6) * S2_ROW)  // 616
#define S1_SIZE (KC * S1_CH)        // 2304
#define S2_SIZE (KC * S2_CH)        // 4928
#define BUF_SIZE (S1_SIZE + S2_SIZE)               // 7232 floats
#define SMEM_BYTES (2 * BUF_SIZE * sizeof(float))  // 57856 B per CTA

typedef unsigned long long ull;

__device__ __forceinline__ uint32_t sptr(const void* p) {
    return (uint32_t)__cvta_generic_to_shared(p);
}
__device__ __forceinline__ void cp16(void* dst, const float* src, bool pred) {
    int bytes = pred ? 16 : 0;
    asm volatile("cp.async.cg.shared.global [%0], [%1], 16, %2;\n"
                 :: "r"(sptr(dst)), "l"(src), "r"(bytes));
}
__device__ __forceinline__ void cp_commit() {
    asm volatile("cp.async.commit_group;\n" ::: "memory");
}
__device__ __forceinline__ void lds2(ull& a, ull& b, uint32_t addr) {
    asm volatile("ld.shared.v2.u64 {%0,%1}, [%2];"
                 : "=l"(a), "=l"(b) : "r"(addr));
}
__device__ __forceinline__ void fma2(ull& d, ull a, ull b) {
    asm("fma.rn.f32x2 %0, %1, %2, %0;" : "+l"(d) : "l"(a), "l"(b));
}
__device__ __forceinline__ void unpack2(float& lo, float& hi, ull v) {
    asm("mov.b64 {%0,%1}, %2;" : "=f"(lo), "=f"(hi) : "l"(v));
}

// Pure shift/mask indexing; 'second' rows loaded as 11 full float4 chunks
// covering padded cols [0,44) = logical x [-4,40); OOB chunks zfill (== jnp.pad).
__device__ __forceinline__ void load_chunk(
    float* __restrict__ s1, float* __restrict__ s2,
    const float* __restrict__ fbase, const float* __restrict__ sbase,
    int c0, int x0, int y0, int tid)
{
    const size_t HW = (size_t)H_ * W_;
    // ---- first tile: 8ch x 8 rows x 8 q = 512 units ----
#pragma unroll
    for (int it = 0; it < 3; ++it) {
        int u = tid + it * NT;
        if (it < 2 || u < 512) {
            int c = u >> 6;
            int row = (u >> 3) & 7;
            int q = u & 7;
            const float* src = fbase + (size_t)(c0 + c) * HW + (size_t)(y0 + row) * W_ + x0 + q * 4;
            cp16(s1 + c * S1_CH + row * S1_ROW + q * 4, src, true);
        }
    }
    // ---- second tile: per channel exactly 14 rows x 16 slots = 224 = NT ----
    const int row = tid >> 4;      // 0..13
    const int q   = tid & 15;      // 0..15, use q < 11
    if (q < 11) {
        const int gy = y0 - 3 + row;
        const int gx = x0 - 4 + q * 4;
        const bool p = (gy >= 0) && (gy < H_) && (gx >= 0) && (gx < W_);
        const int gyc = gy < 0 ? 0 : (gy >= H_ ? H_ - 1 : gy);
        const int gxc = gx < 0 ? 0 : (gx >= W_ ? W_ - 1 : gx);
        const float* src0 = sbase + (size_t)c0 * HW + (size_t)gyc * W_ + gxc;
        float* dst0 = s2 + row * S2_ROW + q * 4;
#pragma unroll
        for (int c = 0; c < KC; ++c)
            cp16(dst0 + c * S2_CH, src0 + c * HW, p);
    }
}

__device__ __forceinline__ void load_ef(
    uint32_t a1, uint32_t a2, ull (&f)[4], ull (&e)[8])
{
    lds2(f[0], f[1], a1);
    lds2(f[2], f[3], a1 + 16);
    lds2(e[0], e[1], a2);
    lds2(e[2], e[3], a2 + 16);
    lds2(e[4], e[5], a2 + 32);
    lds2(e[6], e[7], a2 + 48);
}

__device__ __forceinline__ void compute_ch(
    ull* __restrict__ acc2, const ull (&f)[4], const ull (&e)[8])
{
    ull o[7];
#pragma unroll
    for (int t = 0; t < 7; ++t)
        o[t] = (e[t] >> 32) | (e[t + 1] << 32);
#pragma unroll
    for (int d = 0; d < 7; ++d) {
#pragma unroll
        for (int pp = 0; pp < 4; ++pp) {
            ull vp = (d & 1) ? e[(d + 1) / 2 + pp] : o[d / 2 + pp];
            fma2(acc2[d * 4 + pp], f[pp], vp);
        }
    }
}

__global__ void __launch_bounds__(NT, 2)
corr_kernel(const float* __restrict__ first,
            const float* __restrict__ second,
            float* __restrict__ out)
{
    extern __shared__ float smem[];
    const int tid = threadIdx.x;
    const int dj = tid >> 5;                  // warp = row displacement 0..6
    const int lane = tid & 31;
    // Conflict-free lane map: 8-lane LDS wavefront = 8 consecutive rows.
    const int tyl = lane & 7;                 // 0..7, one y-row
    const int txl = lane >> 3;                // 0..3, owns 8 x-pixels
    const int xl = txl * 8;
    const int bx = blockIdx.x, by = blockIdx.y, b = blockIdx.z;
    const int x0 = bx * TX, y0 = by * TY;

    const size_t HW = (size_t)H_ * W_;
    const float* fbase = first  + (size_t)b * C_ * HW;
    const float* sbase = second + (size_t)b * C_ * HW;

    const uint32_t smem_base = sptr(smem);
    const uint32_t s1_thr = smem_base + (uint32_t)(tyl * S1_ROW + xl) * 4;
    const uint32_t s2_thr = smem_base + (uint32_t)S1_SIZE * 4
                          + (uint32_t)((tyl + dj) * S2_ROW + xl) * 4;

    ull acc2[28];   // [di 0..6][px-pair 0..3]
#pragma unroll
    for (int i = 0; i < 28; ++i) acc2[i] = 0ull;

    load_chunk(smem, smem + S1_SIZE, fbase, sbase, 0, x0, y0, tid);
    cp_commit();

#pragma unroll 1
    for (int k = 0; k < NCHUNK; ++k) {
        if (k < NCHUNK - 1) {
            float* nb = smem + ((k + 1) & 1) * BUF_SIZE;
            load_chunk(nb, nb + S1_SIZE, fbase, sbase, (k + 1) * KC, x0, y0, tid);
            cp_commit();
            asm volatile("cp.async.wait_group 1;\n" ::: "memory");
        } else {
            asm volatile("cp.async.wait_group 0;\n" ::: "memory");
        }
        __syncthreads();

        const uint32_t boff = (uint32_t)((k & 1) * BUF_SIZE * 4);
        uint32_t a1 = s1_thr + boff;
        uint32_t a2 = s2_thr + boff;

        // Register double-buffered channel pipeline: load c+1 before compute c.
        ull f0[4], e0[8], f1[4], e1[8];
        load_ef(a1, a2, f0, e0);                     // c = 0
#pragma unroll
        for (int c = 0; c < KC; c += 2) {
            a1 += S1_CH * 4; a2 += S2_CH * 4;
            load_ef(a1, a2, f1, e1);                 // c+1
            compute_ch(acc2, f0, e0);                // c
            if (c + 2 < KC) {
                a1 += S1_CH * 4; a2 += S2_CH * 4;
                load_ef(a1, a2, f0, e0);             // c+2
            }
            compute_ch(acc2, f1, e1);                // c+1
        }
        __syncthreads();
    }

    // epilogue: mean over channels; warp dj owns flattened d = dj*7 + di
    const float invC = 1.0f / (float)C_;
    const int y = y0 + tyl;
    const int x = x0 + xl;
#pragma unroll
    for (int d = 0; d < 7; ++d) {
        float r[8];
#pragma unroll
        for (int pp = 0; pp < 4; ++pp)
            unpack2(r[pp * 2], r[pp * 2 + 1], acc2[d * 4 + pp]);
        float* op = out + (((size_t)b * ND + dj * 7 + d) * H_ + y) * W_ + x;
        float4 o0, o1;
        o0.x = r[0] * invC; o0.y = r[1] * invC;
        o0.z = r[2] * invC; o0.w = r[3] * invC;
        o1.x = r[4] * invC; o1.y = r[5] * invC;
        o1.z = r[6] * invC; o1.w = r[7] * invC;
        ((float4*)op)[0] = o0;
        ((float4*)op)[1] = o1;
    }
}

extern "C" void kernel_launch(void* const* d_in, const int* in_sizes, int n_in,
                              void* d_out, int out_size)
{
    const float* first  = (const float*)d_in[0];
    const float* second = (const float*)d_in[1];
    float* out = (float*)d_out;

    cudaFuncSetAttribute(corr_kernel,
                         cudaFuncAttributeMaxDynamicSharedMemorySize,
                         (int)SMEM_BYTES);

    dim3 grid(W_ / TX, H_ / TY, B_);   // 14 x 24 x 8 = 2688 CTAs
    dim3 block(NT);
    corr_kernel<<<grid, block, SMEM_BYTES>>>(first, second, out);
}

// round 13
// speedup vs baseline: 1.7151x; 1.0446x over previous
#include <cuda_runtime.h>
#include <cstdint>

#define B_  8
#define C_  128
#define H_  192
#define W_  448
#define ND  49

#define TX  32
#define TY  8
#define KC  8
#define NCHUNK (C_ / KC)
#define NT  224          // 7 warps, warp = dj

#define S1_ROW 36                   // 144B rows: slot stride 9 (odd) -> conflict-free
#define S1_CH  (TY * S1_ROW)        // 288
#define S2_ROW 44                   // 176B rows: slot stride 11 (odd) -> conflict-free
#define S2_CH  ((TY + 6) * S2_ROW)  // 616
#define S1_SIZE (KC * S1_CH)        // 2304
#define S2_SIZE (KC * S2_CH)        // 4928
#define BUF_SIZE (S1_SIZE + S2_SIZE)               // 7232 floats
#define NBUF 3
#define BUF_BYTES (BUF_SIZE * 4)
#define SMEM_BYTES (NBUF * BUF_BYTES)              // 86784 B per CTA

typedef unsigned long long ull;

__device__ __forceinline__ uint32_t sptr(const void* p) {
    return (uint32_t)__cvta_generic_to_shared(p);
}
__device__ __forceinline__ void cp16(void* dst, const float* src, bool pred) {
    int bytes = pred ? 16 : 0;
    asm volatile("cp.async.cg.shared.global [%0], [%1], 16, %2;\n"
                 :: "r"(sptr(dst)), "l"(src), "r"(bytes));
}
__device__ __forceinline__ void cp_commit() {
    asm volatile("cp.async.commit_group;\n" ::: "memory");
}
__device__ __forceinline__ void lds2(ull& a, ull& b, uint32_t addr) {
    asm volatile("ld.shared.v2.u64 {%0,%1}, [%2];"
                 : "=l"(a), "=l"(b) : "r"(addr));
}
__device__ __forceinline__ void fma2(ull& d, ull a, ull b) {
    asm("fma.rn.f32x2 %0, %1, %2, %0;" : "+l"(d) : "l"(a), "l"(b));
}
__device__ __forceinline__ void unpack2(float& lo, float& hi, ull v) {
    asm("mov.b64 {%0,%1}, %2;" : "=f"(lo), "=f"(hi) : "l"(v));
}

// Pure shift/mask indexing; 'second' rows loaded as 11 full float4 chunks
// covering padded cols [0,44) = logical x [-4,40); OOB chunks zfill (== jnp.pad).
__device__ __forceinline__ void load_chunk(
    float* __restrict__ s1, float* __restrict__ s2,
    const float* __restrict__ fbase, const float* __restrict__ sbase,
    int c0, int x0, int y0, int tid)
{
    const size_t HW = (size_t)H_ * W_;
    // ---- first tile: 8ch x 8 rows x 8 q = 512 units ----
#pragma unroll
    for (int it = 0; it < 3; ++it) {
        int u = tid + it * NT;
        if (it < 2 || u < 512) {
            int c = u >> 6;
            int row = (u >> 3) & 7;
            int q = u & 7;
            const float* src = fbase + (size_t)(c0 + c) * HW + (size_t)(y0 + row) * W_ + x0 + q * 4;
            cp16(s1 + c * S1_CH + row * S1_ROW + q * 4, src, true);
        }
    }
    // ---- second tile: per channel exactly 14 rows x 16 slots = 224 = NT ----
    const int row = tid >> 4;      // 0..13
    const int q   = tid & 15;      // 0..15, use q < 11
    if (q < 11) {
        const int gy = y0 - 3 + row;
        const int gx = x0 - 4 + q * 4;
        const bool p = (gy >= 0) && (gy < H_) && (gx >= 0) && (gx < W_);
        const int gyc = gy < 0 ? 0 : (gy >= H_ ? H_ - 1 : gy);
        const int gxc = gx < 0 ? 0 : (gx >= W_ ? W_ - 1 : gx);
        const float* src0 = sbase + (size_t)c0 * HW + (size_t)gyc * W_ + gxc;
        float* dst0 = s2 + row * S2_ROW + q * 4;
#pragma unroll
        for (int c = 0; c < KC; ++c)
            cp16(dst0 + c * S2_CH, src0 + c * HW, p);
    }
}

__device__ __forceinline__ void load_ef(
    uint32_t a1, uint32_t a2, ull (&f)[4], ull (&e)[8])
{
    lds2(f[0], f[1], a1);
    lds2(f[2], f[3], a1 + 16);
    lds2(e[0], e[1], a2);
    lds2(e[2], e[3], a2 + 16);
    lds2(e[4], e[5], a2 + 32);
    lds2(e[6], e[7], a2 + 48);
}

__device__ __forceinline__ void compute_ch(
    ull* __restrict__ acc2, const ull (&f)[4], const ull (&e)[8])
{
    ull o[7];
#pragma unroll
    for (int t = 0; t < 7; ++t)
        o[t] = (e[t] >> 32) | (e[t + 1] << 32);
#pragma unroll
    for (int d = 0; d < 7; ++d) {
#pragma unroll
        for (int pp = 0; pp < 4; ++pp) {
            ull vp = (d & 1) ? e[(d + 1) / 2 + pp] : o[d / 2 + pp];
            fma2(acc2[d * 4 + pp], f[pp], vp);
        }
    }
}

__global__ void __launch_bounds__(NT, 2)
corr_kernel(const float* __restrict__ first,
            const float* __restrict__ second,
            float* __restrict__ out)
{
    extern __shared__ float smem[];
    const int tid = threadIdx.x;
    const int dj = tid >> 5;                  // warp = row displacement 0..6
    const int lane = tid & 31;
    // Conflict-free lane map: 8-lane LDS wavefront = 8 consecutive rows.
    const int tyl = lane & 7;                 // 0..7, one y-row
    const int txl = lane >> 3;                // 0..3, owns 8 x-pixels
    const int xl = txl * 8;
    const int bx = blockIdx.x, by = blockIdx.y, b = blockIdx.z;
    const int x0 = bx * TX, y0 = by * TY;

    const size_t HW = (size_t)H_ * W_;
    const float* fbase = first  + (size_t)b * C_ * HW;
    const float* sbase = second + (size_t)b * C_ * HW;

    const uint32_t smem_base = sptr(smem);
    const uint32_t s1_thr = smem_base + (uint32_t)(tyl * S1_ROW + xl) * 4;
    const uint32_t s2_thr = smem_base + (uint32_t)S1_SIZE * 4
                          + (uint32_t)((tyl + dj) * S2_ROW + xl) * 4;

    ull acc2[28];   // [di 0..6][px-pair 0..3]
#pragma unroll
    for (int i = 0; i < 28; ++i) acc2[i] = 0ull;

    // 3-stage smem pipeline: prologue fills buffers 0 and 1.
    load_chunk(smem, smem + S1_SIZE, fbase, sbase, 0, x0, y0, tid);
    cp_commit();
    load_chunk(smem + BUF_SIZE, smem + BUF_SIZE + S1_SIZE, fbase, sbase, KC, x0, y0, tid);
    cp_commit();

    uint32_t coff = 0;                        // compute buffer byte offset
    int lidx = 2;                             // load buffer index

#pragma unroll 1
    for (int k = 0; k < NCHUNK; ++k) {
        if (k < NCHUNK - 1) {
            asm volatile("cp.async.wait_group 1;\n" ::: "memory");
        } else {
            asm volatile("cp.async.wait_group 0;\n" ::: "memory");
        }
        __syncthreads();   // single barrier per chunk: buffer lidx free, buffer k visible

        if (k + 2 < NCHUNK) {
            float* nb = smem + lidx * BUF_SIZE;
            load_chunk(nb, nb + S1_SIZE, fbase, sbase, (k + 2) * KC, x0, y0, tid);
            cp_commit();
        }

        uint32_t a1 = s1_thr + coff;
        uint32_t a2 = s2_thr + coff;

        // Register double-buffered channel pipeline: load c+1 before compute c.
        ull f0[4], e0[8], f1[4], e1[8];
        load_ef(a1, a2, f0, e0);                     // c = 0
#pragma unroll
        for (int c = 0; c < KC; c += 2) {
            a1 += S1_CH * 4; a2 += S2_CH * 4;
            load_ef(a1, a2, f1, e1);                 // c+1
            compute_ch(acc2, f0, e0);                // c
            if (c + 2 < KC) {
                a1 += S1_CH * 4; a2 += S2_CH * 4;
                load_ef(a1, a2, f0, e0);             // c+2
            }
            compute_ch(acc2, f1, e1);                // c+1
        }

        coff += BUF_BYTES;
        if (coff == NBUF * BUF_BYTES) coff = 0;
        if (++lidx == NBUF) lidx = 0;
    }

    // epilogue: mean over channels; warp dj owns flattened d = dj*7 + di
    const float invC = 1.0f / (float)C_;
    const int y = y0 + tyl;
    const int x = x0 + xl;
#pragma unroll
    for (int d = 0; d < 7; ++d) {
        float r[8];
#pragma unroll
        for (int pp = 0; pp < 4; ++pp)
            unpack2(r[pp * 2], r[pp * 2 + 1], acc2[d * 4 + pp]);
        float* op = out + (((size_t)b * ND + dj * 7 + d) * H_ + y) * W_ + x;
        float4 o0, o1;
        o0.x = r[0] * invC; o0.y = r[1] * invC;
        o0.z = r[2] * invC; o0.w = r[3] * invC;
        o1.x = r[4] * invC; o1.y = r[5] * invC;
        o1.z = r[6] * invC; o1.w = r[7] * invC;
        ((float4*)op)[0] = o0;
        ((float4*)op)[1] = o1;
    }
}

extern "C" void kernel_launch(void* const* d_in, const int* in_sizes, int n_in,
                              void* d_out, int out_size)
{
    const float* first  = (const float*)d_in[0];
    const float* second = (const float*)d_in[1];
    float* out = (float*)d_out;

    cudaFuncSetAttribute(corr_kernel,
                         cudaFuncAttributeMaxDynamicSharedMemorySize,
                         (int)SMEM_BYTES);

    dim3 grid(W_ / TX, H_ / TY, B_);   // 14 x 24 x 8 = 2688 CTAs
    dim3 block(NT);
    corr_kernel<<<grid, block, SMEM_BYTES>>>(first, second, out);
}